// round 16
// baseline (speedup 1.0000x reference)
#include <cuda_runtime.h>
#include <cuda_bf16.h>
#include <cstdint>
#include <math.h>

// Problem constants
#define B_   4
#define S_   2048
#define D_   1024
#define H_   16
#define HD_  64
#define NTOK (B_ * S_)          // 8192
#define N3D  (3 * D_)           // 3072

typedef __nv_bfloat16 bf16;

// ---------------------------------------------------------------------------
// Scratch (static __device__ arrays — allocation-free per harness rules)
// ---------------------------------------------------------------------------
__device__ bf16 g_xh[(size_t)NTOK * D_];      // x split hi
__device__ bf16 g_xl[(size_t)NTOK * D_];      // x split lo
__device__ bf16 g_wqh[(size_t)N3D * D_];      // w_qkv^T split hi [N][K]
__device__ bf16 g_wql[(size_t)N3D * D_];
__device__ bf16 g_woh[(size_t)D_ * D_];       // w_out^T split hi [N][K]
__device__ bf16 g_wol[(size_t)D_ * D_];
__device__ bf16 g_qh[(size_t)NTOK * N3D];     // qkv split hi
__device__ bf16 g_ql[(size_t)NTOK * N3D];     // qkv split lo
__device__ bf16 g_ch[(size_t)NTOK * D_];      // ctx split hi
__device__ bf16 g_cl[(size_t)NTOK * D_];      // ctx split lo

// ---------------------------------------------------------------------------
// PTX helpers — all plain sm_80-era instructions (safe for .target sm_103)
// ---------------------------------------------------------------------------
__device__ __forceinline__ uint32_t smem_u32(const void* p) {
    uint32_t a;
    asm("{ .reg .u64 t; cvta.to.shared.u64 t, %1; cvt.u32.u64 %0, t; }"
        : "=r"(a) : "l"(p));
    return a;
}

#define CP16(dst, src) \
    asm volatile("cp.async.cg.shared.global [%0], [%1], 16;" \
                 :: "r"(dst), "l"(src) : "memory")
#define CP_COMMIT() asm volatile("cp.async.commit_group;" ::: "memory")
#define CP_WAIT(n)  asm volatile("cp.async.wait_group %0;" :: "n"(n) : "memory")

#define LDSM4(r, a) \
    asm volatile("ldmatrix.sync.aligned.m8n8.x4.shared.b16 {%0,%1,%2,%3}, [%4];" \
                 : "=r"((r)[0]), "=r"((r)[1]), "=r"((r)[2]), "=r"((r)[3]) : "r"(a))
#define LDSM4T(r, a) \
    asm volatile("ldmatrix.sync.aligned.m8n8.x4.trans.shared.b16 {%0,%1,%2,%3}, [%4];" \
                 : "=r"((r)[0]), "=r"((r)[1]), "=r"((r)[2]), "=r"((r)[3]) : "r"(a))

#define MMA_BF16(c, a, b0, b1) \
    asm volatile("mma.sync.aligned.m16n8k16.row.col.f32.bf16.bf16.f32 " \
                 "{%0,%1,%2,%3}, {%4,%5,%6,%7}, {%8,%9}, {%0,%1,%2,%3};" \
                 : "+f"((c)[0]), "+f"((c)[1]), "+f"((c)[2]), "+f"((c)[3]) \
                 : "r"((a)[0]), "r"((a)[1]), "r"((a)[2]), "r"((a)[3]), \
                   "r"(b0), "r"(b1))

// raw EX2 (exp2) — __expf emits MUL(log2e)+EX2; we fold log2e into SCALE2.
__device__ __forceinline__ float ex2f(float x) {
    float r;
    asm("ex2.approx.f32 %0, %1;" : "=f"(r) : "f"(x));
    return r;
}

// fp32 pair -> bf16x2 hi word + bf16x2 residual word
__device__ __forceinline__ void split_pack(float a, float b,
                                           uint32_t& hi, uint32_t& lo) {
    bf16 ha = __float2bfloat16(a);
    bf16 hb = __float2bfloat16(b);
    bf16 la = __float2bfloat16(a - __bfloat162float(ha));
    bf16 lb = __float2bfloat16(b - __bfloat162float(hb));
    hi = (uint32_t)__bfloat16_as_ushort(ha) |
         ((uint32_t)__bfloat16_as_ushort(hb) << 16);
    lo = (uint32_t)__bfloat16_as_ushort(la) |
         ((uint32_t)__bfloat16_as_ushort(lb) << 16);
}

// ---------------------------------------------------------------------------
// Split kernels: fp32 -> bf16 hi + bf16 lo (residual)
// ---------------------------------------------------------------------------
__global__ void __launch_bounds__(256)
split_rm_kernel(const float* __restrict__ in, bf16* __restrict__ hi,
                bf16* __restrict__ lo, int n4) {
    int i = blockIdx.x * 256 + threadIdx.x;
    if (i >= n4) return;
    float4 v = ((const float4*)in)[i];
    float f[4] = {v.x, v.y, v.z, v.w};
    uint32_t h01, l01, h23, l23;
    split_pack(f[0], f[1], h01, l01);
    split_pack(f[2], f[3], h23, l23);
    uint2 uh, ul;
    uh.x = h01; uh.y = h23;
    ul.x = l01; ul.y = l23;
    ((uint2*)hi)[i] = uh;
    ((uint2*)lo)[i] = ul;
}

// w[K][N] fp32 -> wT_hi/lo[N][K] bf16 (transpose + split)
__global__ void __launch_bounds__(256)
split_tr_kernel(const float* __restrict__ w, bf16* __restrict__ hiT,
                bf16* __restrict__ loT, int Kdim, int Ndim) {
    __shared__ float s[32][33];
    int n0 = blockIdx.x << 5, k0 = blockIdx.y << 5;
    int tx = threadIdx.x, ty = threadIdx.y;   // (32,8)
#pragma unroll
    for (int i = 0; i < 4; i++) {
        int kk = ty * 4 + i;
        s[kk][tx] = w[(size_t)(k0 + kk) * Ndim + n0 + tx];
    }
    __syncthreads();
#pragma unroll
    for (int i = 0; i < 4; i++) {
        int nn = ty * 4 + i;
        float v = s[tx][nn];
        bf16 h = __float2bfloat16(v);
        bf16 l = __float2bfloat16(v - __bfloat162float(h));
        size_t o = (size_t)(n0 + nn) * Kdim + k0 + tx;
        hiT[o] = h;
        loT[o] = l;
    }
}

// ---------------------------------------------------------------------------
// HMMA split-bf16 GEMM + bias.  (unchanged — measured-best configuration)
//   C[M,N] = A[M,K] @ B^T[N,K] + bias, via Ah*Bh + Ah*Bl + Al*Bh.
// CTA: 128x128 tile, 256 threads, 8 warps (4m x 2n -> 32x64 per warp).
// BK = 32 bf16 per chunk, cp.async 2-stage pipeline, single sync per chunk.
// smem: stage = {Ah,Al,Bh,Bl} 128x(32 pad 40) bf16 = 40960 B; 2 stages.
// ---------------------------------------------------------------------------
#define GS_STAGE 40960
#define GS_TOTAL (2 * GS_STAGE)

__global__ void __launch_bounds__(256, 2)
gemm_mma_kernel(const bf16* __restrict__ Ah, const bf16* __restrict__ Al,
                const bf16* __restrict__ Bh, const bf16* __restrict__ Bl,
                const float* __restrict__ bias,
                float* __restrict__ Cf, bf16* __restrict__ Ch,
                bf16* __restrict__ Cl, int N, int K) {
    extern __shared__ char smem[];
    const int tid = threadIdx.x, lane = tid & 31, wid = tid >> 5;
    const int wm = wid & 3, wn = wid >> 2;
    const int m0 = blockIdx.y << 7, n0 = blockIdx.x << 7;
    const uint32_t sb0 = smem_u32(smem);

    float acc[2][8][4];
#pragma unroll
    for (int a = 0; a < 2; a++)
#pragma unroll
        for (int b = 0; b < 8; b++)
#pragma unroll
            for (int c = 0; c < 4; c++) acc[a][b][c] = 0.f;

    const int nch = K >> 5;

    auto load_stage = [&](int c, int s) {
        uint32_t sb = sb0 + s * GS_STAGE;
        int k0 = c << 5;
#pragma unroll
        for (int i = 0; i < 2; i++) {
            int u = tid + (i << 8);
            int row = u >> 2, c16 = u & 3;
            uint32_t d = sb + row * 80 + c16 * 16;
            size_t aoff = (size_t)(m0 + row) * K + k0 + c16 * 8;
            size_t boff = (size_t)(n0 + row) * K + k0 + c16 * 8;
            CP16(d,         Ah + aoff);
            CP16(d + 10240, Al + aoff);
            CP16(d + 20480, Bh + boff);
            CP16(d + 30720, Bl + boff);
        }
        CP_COMMIT();
    };

    load_stage(0, 0);
    for (int c = 0; c < nch; c++) {
        const int s = c & 1;
        CP_WAIT(0);          // stage s (chunk c) fully landed
        __syncthreads();     // also orders compute(c-1) reads before load below
        if (c + 1 < nch) load_stage(c + 1, s ^ 1);   // overlaps compute(c)

        const uint32_t sA = sb0 + s * GS_STAGE;
        const uint32_t sB = sA + 20480;
#pragma unroll
        for (int kk = 0; kk < 2; kk++) {
            uint32_t ah[2][4], al[2][4];
#pragma unroll
            for (int mt = 0; mt < 2; mt++) {
                uint32_t ra = sA + (wm * 32 + mt * 16 + (lane & 15)) * 80 +
                              kk * 32 + ((lane >> 4) << 4);
                LDSM4(ah[mt], ra);
                LDSM4(al[mt], ra + 10240);
            }
#pragma unroll
            for (int nfp = 0; nfp < 4; nfp++) {
                const int g = lane >> 3;
                uint32_t rb = sB +
                    (wn * 64 + nfp * 16 + ((g >> 1) << 3) + (lane & 7)) * 80 +
                    kk * 32 + ((g & 1) << 4);
                uint32_t bh[4], bl[4];
                LDSM4(bh, rb);
                LDSM4(bl, rb + 10240);
#pragma unroll
                for (int mt = 0; mt < 2; mt++) {
                    MMA_BF16(acc[mt][2 * nfp],     ah[mt], bh[0], bh[1]);
                    MMA_BF16(acc[mt][2 * nfp],     ah[mt], bl[0], bl[1]);
                    MMA_BF16(acc[mt][2 * nfp],     al[mt], bh[0], bh[1]);
                    MMA_BF16(acc[mt][2 * nfp + 1], ah[mt], bh[2], bh[3]);
                    MMA_BF16(acc[mt][2 * nfp + 1], ah[mt], bl[2], bl[3]);
                    MMA_BF16(acc[mt][2 * nfp + 1], al[mt], bh[2], bh[3]);
                }
            }
        }
    }

    // Epilogue: c-frag thread layout rows {T/4, T/4+8}, cols {(T%4)*2, +1}
    const int qr = lane >> 2, qc = (lane & 3) << 1;
#pragma unroll
    for (int mt = 0; mt < 2; mt++)
#pragma unroll
    for (int hh = 0; hh < 2; hh++) {
        int row = m0 + wm * 32 + mt * 16 + hh * 8 + qr;
#pragma unroll
        for (int n = 0; n < 8; n++) {
            int col = n0 + wn * 64 + n * 8 + qc;
            float2 bv = *(const float2*)(bias + col);
            float v0 = acc[mt][n][2 * hh]     + bv.x;
            float v1 = acc[mt][n][2 * hh + 1] + bv.y;
            if (Cf) {
                float2 o; o.x = v0; o.y = v1;
                *(float2*)(Cf + (size_t)row * N + col) = o;
            } else {
                uint32_t hi, lo;
                split_pack(v0, v1, hi, lo);
                *(uint32_t*)(Ch + (size_t)row * N + col) = hi;
                *(uint32_t*)(Cl + (size_t)row * N + col) = lo;
            }
        }
    }
}

// ---------------------------------------------------------------------------
// Flash attention on HMMA, split-bf16 (3-term).
// Grid: (S/128, B*H). Block: 256 threads, 8 warps (16 q-rows each).
// NEW vs R15:
//  - Q fragments hoisted into registers ONCE before the KV loop (they are
//    loop-invariant): 256 -> 8 LDSM4 per warp, kills per-chunk Q smem reads.
//  - softmax uses EX2 directly with 0.125*log2(e) folded into the score
//    scale (removes __expf's hidden FMUL per score).
//  - K/V consumed per-nfp (interleaved) to keep live registers <= 128.
// smem: Q hi/lo 128x(64 pad 72) = 36864 B; 2 KV stages of {Kh,Kl,Vh,Vl}
// 64x72 each = 36864 B/stage. Total 110592 B -> 2 CTAs/SM.
// ---------------------------------------------------------------------------
#define AT_QBYTES   36864
#define AT_STAGE    36864
#define AT_SMEM     (AT_QBYTES + 2 * AT_STAGE)

__global__ void __launch_bounds__(256, 2)
attn_mma_kernel(const bf16* __restrict__ qh, const bf16* __restrict__ ql,
                bf16* __restrict__ ch, bf16* __restrict__ cl) {
    extern __shared__ char smem[];
    const int tid = threadIdx.x, lane = tid & 31, wid = tid >> 5;
    const int q0 = blockIdx.x << 7;
    const int b = blockIdx.y >> 4, h = blockIdx.y & 15;
    const size_t tokQ = (size_t)b * S_ + q0;
    const size_t tokB = (size_t)b * S_;
    const int hofs = h * HD_;
    const uint32_t sb0 = smem_u32(smem);
    const uint32_t sQh = sb0, sQl = sb0 + 18432;

    // ---- Q tile load: 128 rows x 8 x 16B chunk-pairs = 1024; 256 thr x 4
#pragma unroll
    for (int i = 0; i < 4; i++) {
        int u = tid + (i << 8);
        int row = u >> 3, c16 = u & 7;
        size_t go = (tokQ + row) * N3D + hofs + c16 * 8;
        uint32_t d = row * 144 + c16 * 16;
        CP16(sQh + d, qh + go);
        CP16(sQl + d, ql + go);
    }

    auto load_kv = [&](int c, int s) {
        uint32_t sb = sb0 + AT_QBYTES + s * AT_STAGE;
#pragma unroll
        for (int i = 0; i < 2; i++) {
            int u = tid + (i << 8);
            int row = u >> 3, c16 = u & 7;
            size_t tok = (tokB + c * 64 + row) * N3D;
            uint32_t d = sb + row * 144 + c16 * 16;
            CP16(d,         qh + tok + D_ + hofs + c16 * 8);       // K hi
            CP16(d + 9216,  ql + tok + D_ + hofs + c16 * 8);       // K lo
            CP16(d + 18432, qh + tok + 2 * D_ + hofs + c16 * 8);   // V hi
            CP16(d + 27648, ql + tok + 2 * D_ + hofs + c16 * 8);   // V lo
        }
        CP_COMMIT();
    };

    load_kv(0, 0);   // commits group 0 (Q + KV0)

    // ---- wait for Q + KV0, then hoist Q fragments into registers (invariant)
    CP_WAIT(0);
    __syncthreads();
    uint32_t qfh[4][4], qfl[4][4];
#pragma unroll
    for (int kk = 0; kk < 4; kk++) {
        uint32_t ra = sQh + (wid * 16 + (lane & 15)) * 144 +
                      kk * 32 + ((lane >> 4) << 4);
        LDSM4(qfh[kk], ra);
        LDSM4(qfl[kk], ra + 18432);
    }

    float o_[8][4];
    float mrow[2], lrow[2];
#pragma unroll
    for (int n = 0; n < 8; n++)
#pragma unroll
        for (int j = 0; j < 4; j++) o_[n][j] = 0.f;
    mrow[0] = mrow[1] = -INFINITY;
    lrow[0] = lrow[1] = 0.f;

    // scores pre-multiplied by 0.125*log2(e): EX2 gives exp(0.125*s)
    const float SCALE2 = 0.125f * 1.4426950408889634f;

    const int NCH = S_ / 64;   // 32
    for (int c = 0; c < NCH; c++) {
        const int s = c & 1;
        if (c > 0) {
            CP_WAIT(0);      // kv(c) landed
            __syncthreads(); // orders compute(c-1) reads before load below
        }
        if (c + 1 < NCH) load_kv(c + 1, s ^ 1);   // overlaps compute(c)

        const uint32_t sK = sb0 + AT_QBYTES + s * AT_STAGE;
        const uint32_t sV = sK + 18432;

        // ---- S = Q @ K^T (3-term split); warp owns q-rows wid*16..+15
        float s_[8][4];
#pragma unroll
        for (int n = 0; n < 8; n++)
#pragma unroll
            for (int j = 0; j < 4; j++) s_[n][j] = 0.f;

#pragma unroll
        for (int kk = 0; kk < 4; kk++) {
#pragma unroll
            for (int nfp = 0; nfp < 4; nfp++) {
                const int g = lane >> 3;
                uint32_t rk = sK +
                    (nfp * 16 + ((g >> 1) << 3) + (lane & 7)) * 144 +
                    kk * 32 + ((g & 1) << 4);
                uint32_t kh[4], kl[4];
                LDSM4(kh, rk);
                LDSM4(kl, rk + 9216);
                MMA_BF16(s_[2 * nfp],     qfh[kk], kh[0], kh[1]);
                MMA_BF16(s_[2 * nfp],     qfh[kk], kl[0], kl[1]);
                MMA_BF16(s_[2 * nfp],     qfl[kk], kh[0], kh[1]);
                MMA_BF16(s_[2 * nfp + 1], qfh[kk], kh[2], kh[3]);
                MMA_BF16(s_[2 * nfp + 1], qfh[kk], kl[2], kl[3]);
                MMA_BF16(s_[2 * nfp + 1], qfl[kk], kh[2], kh[3]);
            }
        }

        // ---- online softmax in exp2 domain (rows owned by lane-quads)
#pragma unroll
        for (int hh = 0; hh < 2; hh++) {
            float vmax = -INFINITY;
#pragma unroll
            for (int n = 0; n < 8; n++) {
                s_[n][2 * hh]     *= SCALE2;
                s_[n][2 * hh + 1] *= SCALE2;
                vmax = fmaxf(vmax, fmaxf(s_[n][2 * hh], s_[n][2 * hh + 1]));
            }
            vmax = fmaxf(vmax, __shfl_xor_sync(0xffffffffu, vmax, 1));
            vmax = fmaxf(vmax, __shfl_xor_sync(0xffffffffu, vmax, 2));
            float mnew = fmaxf(mrow[hh], vmax);
            float sc = ex2f(mrow[hh] - mnew);   // -inf -> 0 on first chunk
            mrow[hh] = mnew;
            float lsum = 0.f;
#pragma unroll
            for (int n = 0; n < 8; n++) {
                float p0 = ex2f(s_[n][2 * hh]     - mnew);
                float p1 = ex2f(s_[n][2 * hh + 1] - mnew);
                s_[n][2 * hh]     = p0;
                s_[n][2 * hh + 1] = p1;
                lsum += p0 + p1;
                o_[n][2 * hh]     *= sc;
                o_[n][2 * hh + 1] *= sc;
            }
            lsum += __shfl_xor_sync(0xffffffffu, lsum, 1);
            lsum += __shfl_xor_sync(0xffffffffu, lsum, 2);
            lrow[hh] = lrow[hh] * sc + lsum;
        }

        // ---- O += P @ V (P packed from S-frags; V via ldmatrix.trans)
#pragma unroll
        for (int kk = 0; kk < 4; kk++) {
            uint32_t pah[4], pal[4];
            split_pack(s_[2 * kk][0],     s_[2 * kk][1],     pah[0], pal[0]);
            split_pack(s_[2 * kk][2],     s_[2 * kk][3],     pah[1], pal[1]);
            split_pack(s_[2 * kk + 1][0], s_[2 * kk + 1][1], pah[2], pal[2]);
            split_pack(s_[2 * kk + 1][2], s_[2 * kk + 1][3], pah[3], pal[3]);
#pragma unroll
            for (int nfp = 0; nfp < 4; nfp++) {
                const int g = lane >> 3;
                uint32_t rv = sV +
                    (kk * 16 + ((g & 1) << 3) + (lane & 7)) * 144 +
                    (nfp * 16 + ((g >> 1) << 3)) * 2;
                uint32_t vh[4], vl[4];
                LDSM4T(vh, rv);
                LDSM4T(vl, rv + 9216);
                MMA_BF16(o_[2 * nfp],     pah, vh[0], vh[1]);
                MMA_BF16(o_[2 * nfp],     pah, vl[0], vl[1]);
                MMA_BF16(o_[2 * nfp],     pal, vh[0], vh[1]);
                MMA_BF16(o_[2 * nfp + 1], pah, vh[2], vh[3]);
                MMA_BF16(o_[2 * nfp + 1], pah, vl[2], vl[3]);
                MMA_BF16(o_[2 * nfp + 1], pal, vh[2], vh[3]);
            }
        }
    }

    // ---- normalize + split-write ctx (bf16 hi/lo)
    const int qr = lane >> 2, qc = (lane & 3) << 1;
#pragma unroll
    for (int hh = 0; hh < 2; hh++) {
        float inv = 1.0f / lrow[hh];
        int row = q0 + wid * 16 + hh * 8 + qr;
        size_t base = ((size_t)(b * S_ + row)) * D_ + hofs;
#pragma unroll
        for (int n = 0; n < 8; n++) {
            int col = n * 8 + qc;
            float v0 = o_[n][2 * hh]     * inv;
            float v1 = o_[n][2 * hh + 1] * inv;
            uint32_t hi, lo;
            split_pack(v0, v1, hi, lo);
            *(uint32_t*)(ch + base + col) = hi;
            *(uint32_t*)(cl + base + col) = lo;
        }
    }
}

// ---------------------------------------------------------------------------
// Launch
// ---------------------------------------------------------------------------
extern "C" void kernel_launch(void* const* d_in, const int* in_sizes, int n_in,
                              void* d_out, int out_size) {
    const float* x     = (const float*)d_in[0];   // [4,2048,1024]
    const float* w_qkv = (const float*)d_in[1];   // [1024,3072]
    const float* b_qkv = (const float*)d_in[2];   // [3072]
    const float* w_out = (const float*)d_in[3];   // [1024,1024]
    const float* b_out = (const float*)d_in[4];   // [1024]
    float* out = (float*)d_out;

    bf16 *xh, *xl, *wqh, *wql, *woh, *wol, *qh, *ql, *ch, *cl;
    cudaGetSymbolAddress((void**)&xh,  g_xh);
    cudaGetSymbolAddress((void**)&xl,  g_xl);
    cudaGetSymbolAddress((void**)&wqh, g_wqh);
    cudaGetSymbolAddress((void**)&wql, g_wql);
    cudaGetSymbolAddress((void**)&woh, g_woh);
    cudaGetSymbolAddress((void**)&wol, g_wol);
    cudaGetSymbolAddress((void**)&qh,  g_qh);
    cudaGetSymbolAddress((void**)&ql,  g_ql);
    cudaGetSymbolAddress((void**)&ch,  g_ch);
    cudaGetSymbolAddress((void**)&cl,  g_cl);

    cudaFuncSetAttribute(gemm_mma_kernel,
                         cudaFuncAttributeMaxDynamicSharedMemorySize, GS_TOTAL);
    cudaFuncSetAttribute(attn_mma_kernel,
                         cudaFuncAttributeMaxDynamicSharedMemorySize, AT_SMEM);

    // 0) splits
    split_rm_kernel<<<NTOK * D_ / 4 / 256, 256>>>(x, xh, xl, NTOK * D_ / 4);
    split_tr_kernel<<<dim3(N3D / 32, D_ / 32), dim3(32, 8)>>>(w_qkv, wqh, wql, D_, N3D);
    split_tr_kernel<<<dim3(D_ / 32, D_ / 32), dim3(32, 8)>>>(w_out, woh, wol, D_, D_);

    // 1) qkv = x @ w_qkv + b_qkv  -> split bf16 out
    gemm_mma_kernel<<<dim3(N3D / 128, NTOK / 128), 256, GS_TOTAL>>>(
        xh, xl, wqh, wql, b_qkv, nullptr, qh, ql, N3D, D_);

    // 2) flash attention -> ctx (split bf16 out)
    attn_mma_kernel<<<dim3(S_ / 128, B_ * H_), 256, AT_SMEM>>>(qh, ql, ch, cl);

    // 3) out = ctx @ w_out + b_out  (fp32 out)
    gemm_mma_kernel<<<dim3(D_ / 128, NTOK / 128), 256, GS_TOTAL>>>(
        ch, cl, woh, wol, b_out, out, nullptr, nullptr, D_, D_);
}

// round 17
// speedup vs baseline: 1.0480x; 1.0480x over previous
#include <cuda_runtime.h>
#include <cuda_bf16.h>
#include <cstdint>
#include <math.h>

// Problem constants
#define B_   4
#define S_   2048
#define D_   1024
#define H_   16
#define HD_  64
#define NTOK (B_ * S_)          // 8192
#define N3D  (3 * D_)           // 3072

typedef __nv_bfloat16 bf16;

// ---------------------------------------------------------------------------
// Scratch (static __device__ arrays — allocation-free per harness rules)
// ---------------------------------------------------------------------------
__device__ bf16  g_xh[(size_t)NTOK * D_];      // x split hi
__device__ bf16  g_xl[(size_t)NTOK * D_];      // x split lo
__device__ bf16  g_wqh[(size_t)N3D * D_];      // w_qkv^T split hi [N][K]
__device__ bf16  g_wql[(size_t)N3D * D_];
__device__ float g_wot[(size_t)D_ * D_];       // w_out^T tf32-rounded [N][K]
__device__ bf16  g_qh[(size_t)NTOK * N3D];     // qkv split hi
__device__ bf16  g_ql[(size_t)NTOK * N3D];     // qkv split lo
__device__ float g_ct[(size_t)NTOK * D_];      // ctx tf32-rounded fp32

// ---------------------------------------------------------------------------
// PTX helpers — all plain sm_80-era instructions (safe for .target sm_103)
// ---------------------------------------------------------------------------
__device__ __forceinline__ uint32_t smem_u32(const void* p) {
    uint32_t a;
    asm("{ .reg .u64 t; cvta.to.shared.u64 t, %1; cvt.u32.u64 %0, t; }"
        : "=r"(a) : "l"(p));
    return a;
}

#define CP16(dst, src) \
    asm volatile("cp.async.cg.shared.global [%0], [%1], 16;" \
                 :: "r"(dst), "l"(src) : "memory")
#define CP_COMMIT() asm volatile("cp.async.commit_group;" ::: "memory")
#define CP_WAIT(n)  asm volatile("cp.async.wait_group %0;" :: "n"(n) : "memory")

#define LDSM4(r, a) \
    asm volatile("ldmatrix.sync.aligned.m8n8.x4.shared.b16 {%0,%1,%2,%3}, [%4];" \
                 : "=r"((r)[0]), "=r"((r)[1]), "=r"((r)[2]), "=r"((r)[3]) : "r"(a))
#define LDSM4T(r, a) \
    asm volatile("ldmatrix.sync.aligned.m8n8.x4.trans.shared.b16 {%0,%1,%2,%3}, [%4];" \
                 : "=r"((r)[0]), "=r"((r)[1]), "=r"((r)[2]), "=r"((r)[3]) : "r"(a))

#define MMA_BF16(c, a, b0, b1) \
    asm volatile("mma.sync.aligned.m16n8k16.row.col.f32.bf16.bf16.f32 " \
                 "{%0,%1,%2,%3}, {%4,%5,%6,%7}, {%8,%9}, {%0,%1,%2,%3};" \
                 : "+f"((c)[0]), "+f"((c)[1]), "+f"((c)[2]), "+f"((c)[3]) \
                 : "r"((a)[0]), "r"((a)[1]), "r"((a)[2]), "r"((a)[3]), \
                   "r"(b0), "r"(b1))

// tf32 MMA: A-regs passed in PTX order (a0,a1,a2,a3); ldmatrix quadrant order
// is (a0,a2,a1,a3), so call sites pass {r0, r2, r1, r3}.
#define MMA_TF32(c, a0, a1, a2, a3, b0, b1) \
    asm volatile("mma.sync.aligned.m16n8k8.row.col.f32.tf32.tf32.f32 " \
                 "{%0,%1,%2,%3}, {%4,%5,%6,%7}, {%8,%9}, {%0,%1,%2,%3};" \
                 : "+f"((c)[0]), "+f"((c)[1]), "+f"((c)[2]), "+f"((c)[3]) \
                 : "r"(a0), "r"(a1), "r"(a2), "r"(a3), "r"(b0), "r"(b1))

#define CVT_TF32(d, s) asm("cvt.rna.tf32.f32 %0, %1;" : "=f"(d) : "f"(s))

// fp32 pair -> bf16x2 hi word + bf16x2 residual word
__device__ __forceinline__ void split_pack(float a, float b,
                                           uint32_t& hi, uint32_t& lo) {
    bf16 ha = __float2bfloat16(a);
    bf16 hb = __float2bfloat16(b);
    bf16 la = __float2bfloat16(a - __bfloat162float(ha));
    bf16 lb = __float2bfloat16(b - __bfloat162float(hb));
    hi = (uint32_t)__bfloat16_as_ushort(ha) |
         ((uint32_t)__bfloat16_as_ushort(hb) << 16);
    lo = (uint32_t)__bfloat16_as_ushort(la) |
         ((uint32_t)__bfloat16_as_ushort(lb) << 16);
}

// ---------------------------------------------------------------------------
// Prep kernels
// ---------------------------------------------------------------------------
__global__ void __launch_bounds__(256)
split_rm_kernel(const float* __restrict__ in, bf16* __restrict__ hi,
                bf16* __restrict__ lo, int n4) {
    int i = blockIdx.x * 256 + threadIdx.x;
    if (i >= n4) return;
    float4 v = ((const float4*)in)[i];
    float f[4] = {v.x, v.y, v.z, v.w};
    uint32_t h01, l01, h23, l23;
    split_pack(f[0], f[1], h01, l01);
    split_pack(f[2], f[3], h23, l23);
    uint2 uh, ul;
    uh.x = h01; uh.y = h23;
    ul.x = l01; ul.y = l23;
    ((uint2*)hi)[i] = uh;
    ((uint2*)lo)[i] = ul;
}

// w[K][N] fp32 -> wT_hi/lo[N][K] bf16 (transpose + split)
__global__ void __launch_bounds__(256)
split_tr_kernel(const float* __restrict__ w, bf16* __restrict__ hiT,
                bf16* __restrict__ loT, int Kdim, int Ndim) {
    __shared__ float s[32][33];
    int n0 = blockIdx.x << 5, k0 = blockIdx.y << 5;
    int tx = threadIdx.x, ty = threadIdx.y;   // (32,8)
#pragma unroll
    for (int i = 0; i < 4; i++) {
        int kk = ty * 4 + i;
        s[kk][tx] = w[(size_t)(k0 + kk) * Ndim + n0 + tx];
    }
    __syncthreads();
#pragma unroll
    for (int i = 0; i < 4; i++) {
        int nn = ty * 4 + i;
        float v = s[tx][nn];
        bf16 h = __float2bfloat16(v);
        bf16 l = __float2bfloat16(v - __bfloat162float(h));
        size_t o = (size_t)(n0 + nn) * Kdim + k0 + tx;
        hiT[o] = h;
        loT[o] = l;
    }
}

// w[K][N] fp32 -> wT[N][K] tf32-rounded fp32 (transpose + round)
__global__ void __launch_bounds__(256)
cvt_tr_kernel(const float* __restrict__ w, float* __restrict__ wT,
              int Kdim, int Ndim) {
    __shared__ float s[32][33];
    int n0 = blockIdx.x << 5, k0 = blockIdx.y << 5;
    int tx = threadIdx.x, ty = threadIdx.y;   // (32,8)
#pragma unroll
    for (int i = 0; i < 4; i++) {
        int kk = ty * 4 + i;
        s[kk][tx] = w[(size_t)(k0 + kk) * Ndim + n0 + tx];
    }
    __syncthreads();
#pragma unroll
    for (int i = 0; i < 4; i++) {
        int nn = ty * 4 + i;
        float v = s[tx][nn], t;
        CVT_TF32(t, v);
        wT[(size_t)(n0 + nn) * Kdim + k0 + tx] = t;
    }
}

// ---------------------------------------------------------------------------
// HMMA split-bf16 GEMM + bias (GEMM1) — measured-best R7 configuration.
//   C[M,N] = A[M,K] @ B^T[N,K] + bias, via Ah*Bh + Ah*Bl + Al*Bh.
// CTA: 128x128, 256 threads, 8 warps (4m x 2n -> 32x64/warp), BK=32,
// cp.async 2-stage. Output: split bf16 hi/lo (Ch/Cl).
// smem: stage = {Ah,Al,Bh,Bl} 128x(32 pad 40) bf16 = 40960 B; 2 stages.
// ---------------------------------------------------------------------------
#define GS_STAGE 40960
#define GS_TOTAL (2 * GS_STAGE)

__global__ void __launch_bounds__(256, 2)
gemm_mma_kernel(const bf16* __restrict__ Ah, const bf16* __restrict__ Al,
                const bf16* __restrict__ Bh, const bf16* __restrict__ Bl,
                const float* __restrict__ bias,
                bf16* __restrict__ Ch, bf16* __restrict__ Cl, int N, int K) {
    extern __shared__ char smem[];
    const int tid = threadIdx.x, lane = tid & 31, wid = tid >> 5;
    const int wm = wid & 3, wn = wid >> 2;
    const int m0 = blockIdx.y << 7, n0 = blockIdx.x << 7;
    const uint32_t sb0 = smem_u32(smem);

    float acc[2][8][4];
#pragma unroll
    for (int a = 0; a < 2; a++)
#pragma unroll
        for (int b = 0; b < 8; b++)
#pragma unroll
            for (int c = 0; c < 4; c++) acc[a][b][c] = 0.f;

    const int nch = K >> 5;

    auto load_stage = [&](int c, int s) {
        uint32_t sb = sb0 + s * GS_STAGE;
        int k0 = c << 5;
#pragma unroll
        for (int i = 0; i < 2; i++) {
            int u = tid + (i << 8);
            int row = u >> 2, c16 = u & 3;
            uint32_t d = sb + row * 80 + c16 * 16;
            size_t aoff = (size_t)(m0 + row) * K + k0 + c16 * 8;
            size_t boff = (size_t)(n0 + row) * K + k0 + c16 * 8;
            CP16(d,         Ah + aoff);
            CP16(d + 10240, Al + aoff);
            CP16(d + 20480, Bh + boff);
            CP16(d + 30720, Bl + boff);
        }
        CP_COMMIT();
    };

    load_stage(0, 0);
    for (int c = 0; c < nch; c++) {
        const int s = c & 1;
        if (c + 1 < nch) { load_stage(c + 1, s ^ 1); CP_WAIT(1); }
        else             { CP_WAIT(0); }
        __syncthreads();

        const uint32_t sA = sb0 + s * GS_STAGE;
        const uint32_t sB = sA + 20480;
#pragma unroll
        for (int kk = 0; kk < 2; kk++) {
            uint32_t ah[2][4], al[2][4];
#pragma unroll
            for (int mt = 0; mt < 2; mt++) {
                uint32_t ra = sA + (wm * 32 + mt * 16 + (lane & 15)) * 80 +
                              kk * 32 + ((lane >> 4) << 4);
                LDSM4(ah[mt], ra);
                LDSM4(al[mt], ra + 10240);
            }
#pragma unroll
            for (int nfp = 0; nfp < 4; nfp++) {
                const int g = lane >> 3;
                uint32_t rb = sB +
                    (wn * 64 + nfp * 16 + ((g >> 1) << 3) + (lane & 7)) * 80 +
                    kk * 32 + ((g & 1) << 4);
                uint32_t bh[4], bl[4];
                LDSM4(bh, rb);
                LDSM4(bl, rb + 10240);
#pragma unroll
                for (int mt = 0; mt < 2; mt++) {
                    MMA_BF16(acc[mt][2 * nfp],     ah[mt], bh[0], bh[1]);
                    MMA_BF16(acc[mt][2 * nfp],     ah[mt], bl[0], bl[1]);
                    MMA_BF16(acc[mt][2 * nfp],     al[mt], bh[0], bh[1]);
                    MMA_BF16(acc[mt][2 * nfp + 1], ah[mt], bh[2], bh[3]);
                    MMA_BF16(acc[mt][2 * nfp + 1], ah[mt], bl[2], bl[3]);
                    MMA_BF16(acc[mt][2 * nfp + 1], al[mt], bh[2], bh[3]);
                }
            }
        }
        __syncthreads();
    }

    const int qr = lane >> 2, qc = (lane & 3) << 1;
#pragma unroll
    for (int mt = 0; mt < 2; mt++)
#pragma unroll
    for (int hh = 0; hh < 2; hh++) {
        int row = m0 + wm * 32 + mt * 16 + hh * 8 + qr;
#pragma unroll
        for (int n = 0; n < 8; n++) {
            int col = n0 + wn * 64 + n * 8 + qc;
            float2 bv = *(const float2*)(bias + col);
            float v0 = acc[mt][n][2 * hh]     + bv.x;
            float v1 = acc[mt][n][2 * hh + 1] + bv.y;
            uint32_t hi, lo;
            split_pack(v0, v1, hi, lo);
            *(uint32_t*)(Ch + (size_t)row * N + col) = hi;
            *(uint32_t*)(Cl + (size_t)row * N + col) = lo;
        }
    }
}

// ---------------------------------------------------------------------------
// tf32 single-pass GEMM + bias (GEMM2 / final projection — error adds in
// quadrature at the output, no softmax amplification: tf32 is safe here).
//   C[M,N] = A[M,K] @ B^T[N,K] + bias, fp32 out.
// CTA: 128x128, 256 threads, 8 warps (4m x 2n -> 32x64/warp), BK=32 tf32,
// cp.async 2-stage. m16n8k8 tf32 MMA; A/B fragments via b16 ldmatrix on the
// 16-bit view (quadrant order a0,a2,a1,a3 / b0,b1,b0',b1').
// smem: stage = A 128x(128B pad 144) + B 128x144 = 36864 B; 2 stages.
// ---------------------------------------------------------------------------
#define GT_BOFF  18432
#define GT_STAGE 36864
#define GT_TOTAL (2 * GT_STAGE)

__global__ void __launch_bounds__(256, 2)
gemm_tf32_kernel(const float* __restrict__ A, const float* __restrict__ Bw,
                 const float* __restrict__ bias, float* __restrict__ Cf,
                 int N, int K) {
    extern __shared__ char smem[];
    const int tid = threadIdx.x, lane = tid & 31, wid = tid >> 5;
    const int wm = wid & 3, wn = wid >> 2;
    const int m0 = blockIdx.y << 7, n0 = blockIdx.x << 7;
    const uint32_t sb0 = smem_u32(smem);

    float acc[2][8][4];
#pragma unroll
    for (int a = 0; a < 2; a++)
#pragma unroll
        for (int b = 0; b < 8; b++)
#pragma unroll
            for (int c = 0; c < 4; c++) acc[a][b][c] = 0.f;

    const int nch = K >> 5;

    auto load_stage = [&](int c, int s) {
        uint32_t sb = sb0 + s * GT_STAGE;
        int k0 = c << 5;
        // A and B: 128 rows x 8 x 16B chunks each; 256 thr x 4 iters each
#pragma unroll
        for (int i = 0; i < 4; i++) {
            int u = tid + (i << 8);
            int row = u >> 3, c16 = u & 7;
            uint32_t d = sb + row * 144 + c16 * 16;
            CP16(d,           A  + (size_t)(m0 + row) * K + k0 + c16 * 4);
            CP16(d + GT_BOFF, Bw + (size_t)(n0 + row) * K + k0 + c16 * 4);
        }
        CP_COMMIT();
    };

    // ldmatrix quadrant addressing: row = base + (lane&7) + ((lane>>4)<<3),
    // byte-col = +16 if (lane>>3)&1. Gives regs (a0,a2,a1,a3) / (b0,b1,b0',b1').
    const int qrow = (lane & 7) + ((lane >> 4) << 3);
    const int qoff = ((lane >> 3) & 1) << 4;

    load_stage(0, 0);
    for (int c = 0; c < nch; c++) {
        const int s = c & 1;
        if (c + 1 < nch) { load_stage(c + 1, s ^ 1); CP_WAIT(1); }
        else             { CP_WAIT(0); }
        __syncthreads();

        const uint32_t sA = sb0 + s * GT_STAGE;
        const uint32_t sB = sA + GT_BOFF;
#pragma unroll
        for (int k8 = 0; k8 < 4; k8++) {
            uint32_t af[2][4];
#pragma unroll
            for (int mt = 0; mt < 2; mt++) {
                uint32_t ra = sA + (wm * 32 + mt * 16 + qrow) * 144 +
                              k8 * 32 + qoff;
                LDSM4(af[mt], ra);
            }
#pragma unroll
            for (int p = 0; p < 4; p++) {
                uint32_t rb = sB + (wn * 64 + p * 16 + qrow) * 144 +
                              k8 * 32 + qoff;
                uint32_t bb[4];
                LDSM4(bb, rb);
#pragma unroll
                for (int mt = 0; mt < 2; mt++) {
                    MMA_TF32(acc[mt][2 * p],
                             af[mt][0], af[mt][2], af[mt][1], af[mt][3],
                             bb[0], bb[1]);
                    MMA_TF32(acc[mt][2 * p + 1],
                             af[mt][0], af[mt][2], af[mt][1], af[mt][3],
                             bb[2], bb[3]);
                }
            }
        }
        __syncthreads();
    }

    const int qr = lane >> 2, qc = (lane & 3) << 1;
#pragma unroll
    for (int mt = 0; mt < 2; mt++)
#pragma unroll
    for (int hh = 0; hh < 2; hh++) {
        int row = m0 + wm * 32 + mt * 16 + hh * 8 + qr;
#pragma unroll
        for (int n = 0; n < 8; n++) {
            int col = n0 + wn * 64 + n * 8 + qc;
            float2 bv = *(const float2*)(bias + col);
            float2 o;
            o.x = acc[mt][n][2 * hh]     + bv.x;
            o.y = acc[mt][n][2 * hh + 1] + bv.y;
            *(float2*)(Cf + (size_t)row * N + col) = o;
        }
    }
}

// ---------------------------------------------------------------------------
// Flash attention on HMMA, split-bf16 (3-term), term-pass MMA schedule
// (measured-best R9/R13 form). Epilogue now writes ctx as tf32-rounded fp32
// for the tf32 GEMM2.
// Grid: (S/128, B*H). Block: 256 threads, 8 warps (16 q-rows each).
// smem: Q hi/lo 128x(64 pad 72) = 36864 B; 2 KV stages of {Kh,Kl,Vh,Vl}
// 64x72 each = 36864 B/stage. Total 110592 B -> 2 CTAs/SM.
// ---------------------------------------------------------------------------
#define AT_QBYTES   36864
#define AT_STAGE    36864
#define AT_SMEM     (AT_QBYTES + 2 * AT_STAGE)

__global__ void __launch_bounds__(256, 2)
attn_mma_kernel(const bf16* __restrict__ qh, const bf16* __restrict__ ql,
                float* __restrict__ ct) {
    extern __shared__ char smem[];
    const int tid = threadIdx.x, lane = tid & 31, wid = tid >> 5;
    const int q0 = blockIdx.x << 7;
    const int b = blockIdx.y >> 4, h = blockIdx.y & 15;
    const size_t tokQ = (size_t)b * S_ + q0;
    const size_t tokB = (size_t)b * S_;
    const int hofs = h * HD_;
    const uint32_t sb0 = smem_u32(smem);
    const uint32_t sQh = sb0, sQl = sb0 + 18432;

#pragma unroll
    for (int i = 0; i < 4; i++) {
        int u = tid + (i << 8);
        int row = u >> 3, c16 = u & 7;
        size_t go = (tokQ + row) * N3D + hofs + c16 * 8;
        uint32_t d = row * 144 + c16 * 16;
        CP16(sQh + d, qh + go);
        CP16(sQl + d, ql + go);
    }

    auto load_kv = [&](int c, int s) {
        uint32_t sb = sb0 + AT_QBYTES + s * AT_STAGE;
#pragma unroll
        for (int i = 0; i < 2; i++) {
            int u = tid + (i << 8);
            int row = u >> 3, c16 = u & 7;
            size_t tok = (tokB + c * 64 + row) * N3D;
            uint32_t d = sb + row * 144 + c16 * 16;
            CP16(d,         qh + tok + D_ + hofs + c16 * 8);
            CP16(d + 9216,  ql + tok + D_ + hofs + c16 * 8);
            CP16(d + 18432, qh + tok + 2 * D_ + hofs + c16 * 8);
            CP16(d + 27648, ql + tok + 2 * D_ + hofs + c16 * 8);
        }
        CP_COMMIT();
    };

    load_kv(0, 0);

    float o_[8][4];
    float mrow[2], lrow[2];
#pragma unroll
    for (int n = 0; n < 8; n++)
#pragma unroll
        for (int j = 0; j < 4; j++) o_[n][j] = 0.f;
    mrow[0] = mrow[1] = -INFINITY;
    lrow[0] = lrow[1] = 0.f;

    const int NCH = S_ / 64;
    for (int c = 0; c < NCH; c++) {
        const int s = c & 1;
        CP_WAIT(0);
        __syncthreads();
        if (c + 1 < NCH) load_kv(c + 1, s ^ 1);

        const uint32_t sK = sb0 + AT_QBYTES + s * AT_STAGE;
        const uint32_t sV = sK + 18432;

        float s_[8][4];
#pragma unroll
        for (int n = 0; n < 8; n++)
#pragma unroll
            for (int j = 0; j < 4; j++) s_[n][j] = 0.f;

#pragma unroll
        for (int kk = 0; kk < 4; kk++) {
            uint32_t qhf[4], qlf[4];
            {
                uint32_t ra = sQh + (wid * 16 + (lane & 15)) * 144 +
                              kk * 32 + ((lane >> 4) << 4);
                LDSM4(qhf, ra);
                LDSM4(qlf, ra + 18432);
            }
            uint32_t kh[4][4], kl[4][4];
#pragma unroll
            for (int nfp = 0; nfp < 4; nfp++) {
                const int g = lane >> 3;
                uint32_t rk = sK +
                    (nfp * 16 + ((g >> 1) << 3) + (lane & 7)) * 144 +
                    kk * 32 + ((g & 1) << 4);
                LDSM4(kh[nfp], rk);
                LDSM4(kl[nfp], rk + 9216);
            }
#pragma unroll
            for (int nfp = 0; nfp < 4; nfp++) {
                MMA_BF16(s_[2 * nfp],     qhf, kh[nfp][0], kh[nfp][1]);
                MMA_BF16(s_[2 * nfp + 1], qhf, kh[nfp][2], kh[nfp][3]);
            }
#pragma unroll
            for (int nfp = 0; nfp < 4; nfp++) {
                MMA_BF16(s_[2 * nfp],     qhf, kl[nfp][0], kl[nfp][1]);
                MMA_BF16(s_[2 * nfp + 1], qhf, kl[nfp][2], kl[nfp][3]);
            }
#pragma unroll
            for (int nfp = 0; nfp < 4; nfp++) {
                MMA_BF16(s_[2 * nfp],     qlf, kh[nfp][0], kh[nfp][1]);
                MMA_BF16(s_[2 * nfp + 1], qlf, kh[nfp][2], kh[nfp][3]);
            }
        }

        const float SCALE = 0.125f;
#pragma unroll
        for (int hh = 0; hh < 2; hh++) {
            float vmax = -INFINITY;
#pragma unroll
            for (int n = 0; n < 8; n++) {
                s_[n][2 * hh]     *= SCALE;
                s_[n][2 * hh + 1] *= SCALE;
                vmax = fmaxf(vmax, fmaxf(s_[n][2 * hh], s_[n][2 * hh + 1]));
            }
            vmax = fmaxf(vmax, __shfl_xor_sync(0xffffffffu, vmax, 1));
            vmax = fmaxf(vmax, __shfl_xor_sync(0xffffffffu, vmax, 2));
            float mnew = fmaxf(mrow[hh], vmax);
            float sc = __expf(mrow[hh] - mnew);
            mrow[hh] = mnew;
            float lsum = 0.f;
#pragma unroll
            for (int n = 0; n < 8; n++) {
                float p0 = __expf(s_[n][2 * hh]     - mnew);
                float p1 = __expf(s_[n][2 * hh + 1] - mnew);
                s_[n][2 * hh]     = p0;
                s_[n][2 * hh + 1] = p1;
                lsum += p0 + p1;
                o_[n][2 * hh]     *= sc;
                o_[n][2 * hh + 1] *= sc;
            }
            lsum += __shfl_xor_sync(0xffffffffu, lsum, 1);
            lsum += __shfl_xor_sync(0xffffffffu, lsum, 2);
            lrow[hh] = lrow[hh] * sc + lsum;
        }

#pragma unroll
        for (int kk = 0; kk < 4; kk++) {
            uint32_t pah[4], pal[4];
            split_pack(s_[2 * kk][0],     s_[2 * kk][1],     pah[0], pal[0]);
            split_pack(s_[2 * kk][2],     s_[2 * kk][3],     pah[1], pal[1]);
            split_pack(s_[2 * kk + 1][0], s_[2 * kk + 1][1], pah[2], pal[2]);
            split_pack(s_[2 * kk + 1][2], s_[2 * kk + 1][3], pah[3], pal[3]);
            uint32_t vh[4][4], vl[4][4];
#pragma unroll
            for (int nfp = 0; nfp < 4; nfp++) {
                const int g = lane >> 3;
                uint32_t rv = sV +
                    (kk * 16 + ((g & 1) << 3) + (lane & 7)) * 144 +
                    (nfp * 16 + ((g >> 1) << 3)) * 2;
                LDSM4T(vh[nfp], rv);
                LDSM4T(vl[nfp], rv + 9216);
            }
#pragma unroll
            for (int nfp = 0; nfp < 4; nfp++) {
                MMA_BF16(o_[2 * nfp],     pah, vh[nfp][0], vh[nfp][1]);
                MMA_BF16(o_[2 * nfp + 1], pah, vh[nfp][2], vh[nfp][3]);
            }
#pragma unroll
            for (int nfp = 0; nfp < 4; nfp++) {
                MMA_BF16(o_[2 * nfp],     pah, vl[nfp][0], vl[nfp][1]);
                MMA_BF16(o_[2 * nfp + 1], pah, vl[nfp][2], vl[nfp][3]);
            }
#pragma unroll
            for (int nfp = 0; nfp < 4; nfp++) {
                MMA_BF16(o_[2 * nfp],     pal, vh[nfp][0], vh[nfp][1]);
                MMA_BF16(o_[2 * nfp + 1], pal, vh[nfp][2], vh[nfp][3]);
            }
        }
    }

    // ---- normalize + write ctx as tf32-rounded fp32 (GEMM2 consumes tf32)
    const int qr = lane >> 2, qc = (lane & 3) << 1;
#pragma unroll
    for (int hh = 0; hh < 2; hh++) {
        float inv = 1.0f / lrow[hh];
        int row = q0 + wid * 16 + hh * 8 + qr;
        size_t base = ((size_t)(b * S_ + row)) * D_ + hofs;
#pragma unroll
        for (int n = 0; n < 8; n++) {
            int col = n * 8 + qc;
            float v0 = o_[n][2 * hh]     * inv;
            float v1 = o_[n][2 * hh + 1] * inv;
            float t0, t1;
            CVT_TF32(t0, v0);
            CVT_TF32(t1, v1);
            float2 o2; o2.x = t0; o2.y = t1;
            *(float2*)(ct + base + col) = o2;
        }
    }
}

// ---------------------------------------------------------------------------
// Launch
// ---------------------------------------------------------------------------
extern "C" void kernel_launch(void* const* d_in, const int* in_sizes, int n_in,
                              void* d_out, int out_size) {
    const float* x     = (const float*)d_in[0];   // [4,2048,1024]
    const float* w_qkv = (const float*)d_in[1];   // [1024,3072]
    const float* b_qkv = (const float*)d_in[2];   // [3072]
    const float* w_out = (const float*)d_in[3];   // [1024,1024]
    const float* b_out = (const float*)d_in[4];   // [1024]
    float* out = (float*)d_out;

    bf16 *xh, *xl, *wqh, *wql, *qh, *ql;
    float *wot, *ct;
    cudaGetSymbolAddress((void**)&xh,  g_xh);
    cudaGetSymbolAddress((void**)&xl,  g_xl);
    cudaGetSymbolAddress((void**)&wqh, g_wqh);
    cudaGetSymbolAddress((void**)&wql, g_wql);
    cudaGetSymbolAddress((void**)&wot, g_wot);
    cudaGetSymbolAddress((void**)&qh,  g_qh);
    cudaGetSymbolAddress((void**)&ql,  g_ql);
    cudaGetSymbolAddress((void**)&ct,  g_ct);

    cudaFuncSetAttribute(gemm_mma_kernel,
                         cudaFuncAttributeMaxDynamicSharedMemorySize, GS_TOTAL);
    cudaFuncSetAttribute(gemm_tf32_kernel,
                         cudaFuncAttributeMaxDynamicSharedMemorySize, GT_TOTAL);
    cudaFuncSetAttribute(attn_mma_kernel,
                         cudaFuncAttributeMaxDynamicSharedMemorySize, AT_SMEM);

    // 0) prep
    split_rm_kernel<<<NTOK * D_ / 4 / 256, 256>>>(x, xh, xl, NTOK * D_ / 4);
    split_tr_kernel<<<dim3(N3D / 32, D_ / 32), dim3(32, 8)>>>(w_qkv, wqh, wql, D_, N3D);
    cvt_tr_kernel<<<dim3(D_ / 32, D_ / 32), dim3(32, 8)>>>(w_out, wot, D_, D_);

    // 1) qkv = x @ w_qkv + b_qkv  (split-bf16 3-term; output split bf16)
    gemm_mma_kernel<<<dim3(N3D / 128, NTOK / 128), 256, GS_TOTAL>>>(
        xh, xl, wqh, wql, b_qkv, qh, ql, N3D, D_);

    // 2) flash attention -> ctx (tf32-rounded fp32 out)
    attn_mma_kernel<<<dim3(S_ / 128, B_ * H_), 256, AT_SMEM>>>(qh, ql, ct);

    // 3) out = ctx @ w_out + b_out  (single-pass tf32)
    gemm_tf32_kernel<<<dim3(D_ / 128, NTOK / 128), 256, GT_TOTAL>>>(
        ct, wot, b_out, out, D_, D_);
}